// round 13
// baseline (speedup 1.0000x reference)
#include <cuda_runtime.h>
#include <cuda/atomic>

// Problem shape (fixed by the dataset)
#define BB 32
#define AA 32768
#define CC 21
#define TILE 256
#define HB 4096                // level-0 bins: key bits 31:20
#define RB 2048                // refine bins:  key bits 19:9
#define STH 256                // select threads per block (8 warps: cheap barriers)
#define FULLM 0xFFFFFFFFu

// ---------------- scratch (zero-initialized BSS; left zeroed after each call) --
__device__ float    g_ce[BB * AA];      // per-anchor CE (4 MB)
__device__ unsigned g_hist[BB * HB];    // per-row hist of key bits 31:20
__device__ int      g_numpos[BB];
__device__ double   g_locr[BB];
__device__ double   g_pcer[BB];
__device__ double   g_fsum;
__device__ int      g_fnp;
__device__ int      g_ticket;

// ---------------- helpers ----------------
__device__ __forceinline__ unsigned tokey(float f) {
    unsigned u = __float_as_uint(f);
    return u ^ ((u & 0x80000000u) ? 0xFFFFFFFFu : 0x80000000u);  // order-preserving
}
__device__ __forceinline__ float fromkey(unsigned k) {
    unsigned u = (k & 0x80000000u) ? (k ^ 0x80000000u) : ~k;
    return __uint_as_float(u);
}
__device__ __forceinline__ int fetch_add_acqrel(int* p) {
    cuda::atomic_ref<int, cuda::thread_scope_device> a(*p);
    return a.fetch_add(1, cuda::memory_order_acq_rel);
}

// inclusive suffix scan over 256 threads / 8 warps (all lanes shuffle)
__device__ __forceinline__ unsigned sscan256(unsigned v, int tid) {
    __shared__ unsigned s_wt[8];
    const int lane = tid & 31, w = tid >> 5;
    #pragma unroll
    for (int off = 1; off < 32; off <<= 1) {
        unsigned o = __shfl_down_sync(FULLM, v, off);
        if (lane + off < 32) v += o;
    }
    if (lane == 0) s_wt[w] = v;
    __syncthreads();
    if (w == 0) {                            // ALL 32 lanes shuffle (R8 lesson)
        unsigned x  = (lane < 8) ? s_wt[lane] : 0u;
        unsigned t2 = x;
        #pragma unroll
        for (int off = 1; off < 8; off <<= 1) {
            unsigned o = __shfl_down_sync(FULLM, t2, off);
            if (lane + off < 32) t2 += o;
        }
        if (lane < 8) s_wt[lane] = t2 - x;   // strict suffix of warp totals
    }
    __syncthreads();
    v += s_wt[w];
    __syncthreads();                         // protect s_wt reuse
    return v;
}

// block-wide double sum over 256 threads, valid in tid 0 (all lanes shuffle)
__device__ __forceinline__ double dsum256(double v, int tid) {
    __shared__ double s_d[8];
    const int lane = tid & 31, w = tid >> 5;
    #pragma unroll
    for (int o = 16; o; o >>= 1) v += __shfl_down_sync(FULLM, v, o);
    if (lane == 0) s_d[w] = v;
    __syncthreads();
    double r = 0.0;
    if (w == 0) {
        double x = (lane < 8) ? s_d[lane] : 0.0;
        #pragma unroll
        for (int o = 16; o; o >>= 1) x += __shfl_down_sync(FULLM, x, o);
        r = x;
    }
    __syncthreads();
    return r;
}

// ---------------- kernel 1: CE + loc loss + per-row count histogram ------------
// Byte-identical to the proven ~24us R5 version. Untouched.
__global__ void __launch_bounds__(TILE) ce_kernel(
    const float* __restrict__ loc_p, const float* __restrict__ loc_t,
    const float* __restrict__ cls_p, const int* __restrict__ cls_t)
{
    __shared__ float sh[TILE * CC];
    __shared__ int    s_cnt[8];
    __shared__ double s_loc[8], s_pce[8];

    const int b   = blockIdx.y;
    const int a0  = blockIdx.x * TILE;
    const int tid = threadIdx.x;

    {   // coalesced float4 staging of 256x21 logits
        const float4* src = (const float4*)(cls_p + (size_t)(b * AA + a0) * CC);
        float4* dst = (float4*)sh;
        const int n4 = TILE * CC / 4;
        #pragma unroll
        for (int i = tid; i < n4; i += TILE) dst[i] = src[i];
    }
    __syncthreads();

    const int a  = a0 + tid;
    const int ct = cls_t[b * AA + a];
    const float* row = sh + tid * CC;    // stride 21 -> conflict-free

    float mx = row[0];
    #pragma unroll
    for (int c = 1; c < CC; ++c) mx = fmaxf(mx, row[c]);
    float s = 0.f;
    #pragma unroll
    for (int c = 0; c < CC; ++c) s += __expf(row[c] - mx);
    const int tgt = (ct < 0) ? 0 : ct;
    const float ce = mx + __logf(s) - row[tgt];
    g_ce[b * AA + a] = ce;

    {   // warp-aggregated count histogram (key bits 31:20)
        const unsigned dg    = tokey(ce) >> 20;
        const unsigned peers = __match_any_sync(FULLM, dg);
        if ((tid & 31) == (unsigned)(__ffs(peers) - 1))
            atomicAdd(&g_hist[b * HB + dg], (unsigned)__popc(peers));
    }

    const bool pos = (ct > 0);
    float locs = 0.f;
    if (pos) {
        float4 p = ((const float4*)loc_p)[b * AA + a];
        float4 t = ((const float4*)loc_t)[b * AA + a];
        float d;
        d = fabsf(p.x - t.x); locs += (d < 1.f) ? 0.5f * d * d : d - 0.5f;
        d = fabsf(p.y - t.y); locs += (d < 1.f) ? 0.5f * d * d : d - 0.5f;
        d = fabsf(p.z - t.z); locs += (d < 1.f) ? 0.5f * d * d : d - 0.5f;
        d = fabsf(p.w - t.w); locs += (d < 1.f) ? 0.5f * d * d : d - 0.5f;
    }

    int    cnt = pos ? 1 : 0;
    double dl  = (double)locs;
    double dp  = pos ? (double)ce : 0.0;
    #pragma unroll
    for (int o = 16; o; o >>= 1) {
        cnt += __shfl_down_sync(FULLM, cnt, o);
        dl  += __shfl_down_sync(FULLM, dl, o);
        dp  += __shfl_down_sync(FULLM, dp, o);
    }
    const int w = tid >> 5, l = tid & 31;
    if (l == 0) { s_cnt[w] = cnt; s_loc[w] = dl; s_pce[w] = dp; }
    __syncthreads();
    if (w == 0) {
        int    c2 = (l < 8) ? s_cnt[l] : 0;
        double l2 = (l < 8) ? s_loc[l] : 0.0;
        double p2 = (l < 8) ? s_pce[l] : 0.0;
        #pragma unroll
        for (int o = 4; o; o >>= 1) {
            c2 += __shfl_down_sync(FULLM, c2, o);
            l2 += __shfl_down_sync(FULLM, l2, o);
            p2 += __shfl_down_sync(FULLM, p2, o);
        }
        if (l == 0) {
            if (c2)        atomicAdd(&g_numpos[b], c2);
            if (l2 != 0.0) atomicAdd(&g_locr[b], l2);
            if (p2 != 0.0) atomicAdd(&g_pcer[b], p2);
        }
    }
}

// -------- kernel 2: one 256-thread block/row, barrier-lean, one fused dsum -----
__global__ void __launch_bounds__(STH) select_kernel(float* __restrict__ out)
{
    const int b = blockIdx.x, tid = threadIdx.x;

    __shared__ unsigned s_c[RB];        // refine count hist (8 KB)
    __shared__ float    s_s[RB];        // refine sum hist   (8 KB)
    __shared__ unsigned s_d0, s_kr, s_cb, s_d1, s_k2;

    const int np = g_numpos[b];         // complete: kernel boundary ordered it
    long long kk = 3LL * np; if (kk > AA) kk = AA;
    const unsigned k = (unsigned)kk;

    double rowtot = 0.0;

    if (k > 0) {
        // ---- load my 16 hist bins; zero refine hists before the scan barriers --
        uint4 cv[4];
        {
            const uint4* hp = (const uint4*)(g_hist + b * HB + tid * 16);
            #pragma unroll
            for (int q = 0; q < 4; ++q) cv[q] = hp[q];
        }
        #pragma unroll
        for (int j = 0; j < RB / STH; ++j) {     // 8 bins/thread
            s_c[tid + j * STH] = 0u;
            s_s[tid + j * STH] = 0.f;
        }
        unsigned c16[16]; unsigned tot = 0;
        #pragma unroll
        for (int q = 0; q < 4; ++q) {
            c16[q*4+0] = cv[q].x; c16[q*4+1] = cv[q].y;
            c16[q*4+2] = cv[q].z; c16[q*4+3] = cv[q].w;
            tot += cv[q].x + cv[q].y + cv[q].z + cv[q].w;
        }

        // ---- bracket k over 4096 bins (16/thread) ----
        const unsigned A = sscan256(tot, tid);
        unsigned ab = A - tot;                   // strictly above my 16 bins
        #pragma unroll
        for (int j = 15; j >= 0; --j) {          // high bin -> low bin
            if (ab < k && k <= ab + c16[j]) {
                s_d0 = (unsigned)(tid * 16 + j); s_kr = k - ab; s_cb = c16[j];
            }
            ab += c16[j];
        }
        __syncthreads();                         // publish d0 + refine zeros
        const unsigned d0 = s_d0, krem = s_kr, cbin = s_cb;

        // ---- one row pass: 32 float4/thread, prefetched in groups of 8 --------
        double sumA = 0.0;
        {
            const float4* row4 = (const float4*)(g_ce + (size_t)b * AA);
            #pragma unroll
            for (int g = 0; g < 4; ++g) {
                float4 r[8];
                #pragma unroll
                for (int it = 0; it < 8; ++it)   // independent loads: batched
                    r[it] = __ldcg(row4 + tid + (g * 8 + it) * STH);
                #pragma unroll
                for (int it = 0; it < 8; ++it) {
                    const float xs[4] = {r[it].x, r[it].y, r[it].z, r[it].w};
                    #pragma unroll
                    for (int e = 0; e < 4; ++e) {
                        const float x = xs[e];
                        const unsigned key = tokey(x);
                        const unsigned dg  = key >> 20;
                        if (dg > d0) sumA += (double)x;
                        else if (dg == d0) {             // ~3-5%: spread bins
                            const unsigned rr = (key >> 9) & (RB - 1u);
                            atomicAdd(&s_c[rr], 1u);
                            atomicAdd(&s_s[rr], x);
                        }
                    }
                }
            }
        }
        __syncthreads();

        // ---- per-thread local share of the in-bin sum, then ONE fused dsum ----
        double local = sumA;
        if (krem == cbin) {
            // whole boundary bin included: each thread adds its 8 refine bins
            #pragma unroll
            for (int j = 0; j < RB / STH; ++j)
                local += (double)s_s[tid + j * STH];
        } else {
            // bracket krem in the refine hist (8 consecutive bins/thread)
            unsigned c8[8]; unsigned t8 = 0;
            #pragma unroll
            for (int j = 0; j < 8; ++j) { c8[j] = s_c[tid * 8 + j]; t8 += c8[j]; }
            const unsigned A2 = sscan256(t8, tid);
            unsigned ab2 = A2 - t8;
            #pragma unroll
            for (int j = 7; j >= 0; --j) {
                if (ab2 < krem && krem <= ab2 + c8[j]) {
                    s_d1 = (unsigned)(tid * 8 + j); s_k2 = krem - ab2;
                }
                ab2 += c8[j];
            }
            __syncthreads();
            const unsigned d1 = s_d1, k2 = s_k2;
            #pragma unroll
            for (int j = 0; j < 8; ++j)
                if ((unsigned)(tid * 8 + j) > d1) local += (double)s_s[tid * 8 + j];
            if (tid == 0)                // ties at 23-bit prefix base (err<=2^-14)
                local += (double)k2 * (double)fromkey((d0 << 20) | (d1 << 9));
        }
        const double t = dsum256(local, tid);
        if (tid == 0) rowtot = t;
    }

    // ---- reset this row's histogram for the next graph replay (16 bins/thread)
    {
        uint4* hp = (uint4*)(g_hist + b * HB + tid * 16);
        #pragma unroll
        for (int q = 0; q < 4; ++q) hp[q] = make_uint4(0u, 0u, 0u, 0u);
    }

    if (tid == 0) {
        rowtot += g_locr[b] + g_pcer[b];
        atomicAdd(&g_fsum, rowtot);      // fire-and-forget REDs
        atomicAdd(&g_fnp, np);
        g_locr[b] = 0.0; g_pcer[b] = 0.0; g_numpos[b] = 0;
        const int tk = fetch_add_acqrel(&g_ticket);   // 32 total: negligible
        if (tk == BB - 1) {              // global last finisher
            const double fs = atomicAdd(&g_fsum, 0.0);
            const int    fn = atomicAdd(&g_fnp, 0);
            out[0] = (float)(fs / (double)fn);
            g_fsum = 0.0; g_fnp = 0; g_ticket = 0;
        }
    }
}

// ---------------- launch (2 kernels) ----------------
extern "C" void kernel_launch(void* const* d_in, const int* in_sizes, int n_in,
                              void* d_out, int out_size)
{
    const float* loc_p = (const float*)d_in[0];
    const float* loc_t = (const float*)d_in[1];
    const float* cls_p = (const float*)d_in[2];
    const int*   cls_t = (const int*)d_in[3];

    dim3 grid1(AA / TILE, BB);
    ce_kernel<<<grid1, TILE>>>(loc_p, loc_t, cls_p, cls_t);
    select_kernel<<<BB, STH>>>((float*)d_out);
}

// round 14
// speedup vs baseline: 1.3684x; 1.3684x over previous
#include <cuda_runtime.h>
#include <cuda/atomic>

// Problem shape (fixed by the dataset)
#define BB 32
#define AA 32768
#define CC 21
#define TILE 256
#define HB 4096                // level-0 bins: key bits 31:20
#define RB 2048                // refine bins:  key bits 19:9
#define FULLM 0xFFFFFFFFu

// ---------------- scratch (zero-initialized BSS; left zeroed after each call) --
__device__ float    g_ce[BB * AA];      // per-anchor CE (4 MB)
__device__ unsigned g_hist[BB * HB];    // per-row hist of key bits 31:20
__device__ int      g_numpos[BB];
__device__ double   g_locr[BB];
__device__ double   g_pcer[BB];
__device__ double   g_fsum;
__device__ int      g_fnp;
__device__ int      g_ticket;

// ---------------- helpers ----------------
__device__ __forceinline__ unsigned tokey(float f) {
    unsigned u = __float_as_uint(f);
    return u ^ ((u & 0x80000000u) ? 0xFFFFFFFFu : 0x80000000u);  // order-preserving
}
__device__ __forceinline__ float fromkey(unsigned k) {
    unsigned u = (k & 0x80000000u) ? (k ^ 0x80000000u) : ~k;
    return __uint_as_float(u);
}
__device__ __forceinline__ int fetch_add_acqrel(int* p) {
    cuda::atomic_ref<int, cuda::thread_scope_device> a(*p);
    return a.fetch_add(1, cuda::memory_order_acq_rel);
}

// inclusive suffix scan over 1024 block threads (proven: all lanes shuffle)
__device__ __forceinline__ unsigned suffix_scan(unsigned v, int tid) {
    __shared__ unsigned s_wt[32];
    const int lane = tid & 31, w = tid >> 5;
    #pragma unroll
    for (int off = 1; off < 32; off <<= 1) {
        unsigned o = __shfl_down_sync(FULLM, v, off);
        if (lane + off < 32) v += o;
    }
    if (lane == 0) s_wt[w] = v;
    __syncthreads();
    if (w == 0) {
        unsigned x = s_wt[lane], t2 = x;
        #pragma unroll
        for (int off = 1; off < 32; off <<= 1) {
            unsigned o = __shfl_down_sync(FULLM, t2, off);
            if (lane + off < 32) t2 += o;
        }
        s_wt[lane] = t2 - x;             // strict suffix of warp totals
    }
    __syncthreads();
    v += s_wt[w];
    __syncthreads();
    return v;
}

// block-wide double sum over 1024 threads, valid in tid 0 (all lanes shuffle)
__device__ __forceinline__ double dsum(double v, int tid) {
    __shared__ double s_d[32];
    const int lane = tid & 31, w = tid >> 5;
    #pragma unroll
    for (int o = 16; o; o >>= 1) v += __shfl_down_sync(FULLM, v, o);
    if (lane == 0) s_d[w] = v;
    __syncthreads();
    double r = 0.0;
    if (w == 0) {
        double x = s_d[lane];
        #pragma unroll
        for (int o = 16; o; o >>= 1) x += __shfl_down_sync(FULLM, x, o);
        r = x;
    }
    __syncthreads();
    return r;
}

// ---------------- kernel 1: CE + loc loss + per-row count histogram ------------
// Byte-identical to the proven ~24us R5 version. Untouched.
__global__ void __launch_bounds__(TILE) ce_kernel(
    const float* __restrict__ loc_p, const float* __restrict__ loc_t,
    const float* __restrict__ cls_p, const int* __restrict__ cls_t)
{
    __shared__ float sh[TILE * CC];
    __shared__ int    s_cnt[8];
    __shared__ double s_loc[8], s_pce[8];

    const int b   = blockIdx.y;
    const int a0  = blockIdx.x * TILE;
    const int tid = threadIdx.x;

    {   // coalesced float4 staging of 256x21 logits
        const float4* src = (const float4*)(cls_p + (size_t)(b * AA + a0) * CC);
        float4* dst = (float4*)sh;
        const int n4 = TILE * CC / 4;
        #pragma unroll
        for (int i = tid; i < n4; i += TILE) dst[i] = src[i];
    }
    __syncthreads();

    const int a  = a0 + tid;
    const int ct = cls_t[b * AA + a];
    const float* row = sh + tid * CC;    // stride 21 -> conflict-free

    float mx = row[0];
    #pragma unroll
    for (int c = 1; c < CC; ++c) mx = fmaxf(mx, row[c]);
    float s = 0.f;
    #pragma unroll
    for (int c = 0; c < CC; ++c) s += __expf(row[c] - mx);
    const int tgt = (ct < 0) ? 0 : ct;
    const float ce = mx + __logf(s) - row[tgt];
    g_ce[b * AA + a] = ce;

    {   // warp-aggregated count histogram (key bits 31:20)
        const unsigned dg    = tokey(ce) >> 20;
        const unsigned peers = __match_any_sync(FULLM, dg);
        if ((tid & 31) == (unsigned)(__ffs(peers) - 1))
            atomicAdd(&g_hist[b * HB + dg], (unsigned)__popc(peers));
    }

    const bool pos = (ct > 0);
    float locs = 0.f;
    if (pos) {
        float4 p = ((const float4*)loc_p)[b * AA + a];
        float4 t = ((const float4*)loc_t)[b * AA + a];
        float d;
        d = fabsf(p.x - t.x); locs += (d < 1.f) ? 0.5f * d * d : d - 0.5f;
        d = fabsf(p.y - t.y); locs += (d < 1.f) ? 0.5f * d * d : d - 0.5f;
        d = fabsf(p.z - t.z); locs += (d < 1.f) ? 0.5f * d * d : d - 0.5f;
        d = fabsf(p.w - t.w); locs += (d < 1.f) ? 0.5f * d * d : d - 0.5f;
    }

    int    cnt = pos ? 1 : 0;
    double dl  = (double)locs;
    double dp  = pos ? (double)ce : 0.0;
    #pragma unroll
    for (int o = 16; o; o >>= 1) {
        cnt += __shfl_down_sync(FULLM, cnt, o);
        dl  += __shfl_down_sync(FULLM, dl, o);
        dp  += __shfl_down_sync(FULLM, dp, o);
    }
    const int w = tid >> 5, l = tid & 31;
    if (l == 0) { s_cnt[w] = cnt; s_loc[w] = dl; s_pce[w] = dp; }
    __syncthreads();
    if (w == 0) {
        int    c2 = (l < 8) ? s_cnt[l] : 0;
        double l2 = (l < 8) ? s_loc[l] : 0.0;
        double p2 = (l < 8) ? s_pce[l] : 0.0;
        #pragma unroll
        for (int o = 4; o; o >>= 1) {
            c2 += __shfl_down_sync(FULLM, c2, o);
            l2 += __shfl_down_sync(FULLM, l2, o);
            p2 += __shfl_down_sync(FULLM, p2, o);
        }
        if (l == 0) {
            if (c2)        atomicAdd(&g_numpos[b], c2);
            if (l2 != 0.0) atomicAdd(&g_locr[b], l2);
            if (p2 != 0.0) atomicAdd(&g_pcer[b], p2);
        }
    }
}

// ------ kernel 2: 1024 thr/row; ALL loads issued first, bracket under latency --
__global__ void __launch_bounds__(1024) select_kernel(float* __restrict__ out)
{
    const int b = blockIdx.x, tid = threadIdx.x;

    __shared__ unsigned s_c[RB];        // refine count hist (8 KB)
    __shared__ float    s_s[RB];        // refine sum hist   (8 KB)
    __shared__ unsigned s_d0, s_kr, s_cb, s_d1, s_k2;

    // ===== issue EVERY independent load up front (row data, hist, np) =========
    const float4* row4 = (const float4*)(g_ce + (size_t)b * AA);
    float4 r[8];
    #pragma unroll
    for (int it = 0; it < 8; ++it)           // 4 MB row stream: longest latency
        r[it] = __ldcg(row4 + tid + it * 1024);
    const uint4 cv = __ldcg((const uint4*)(g_hist + b * HB + tid * 4));
    const int np = g_numpos[b];

    // zero refine hists while loads are in flight
    s_c[tid] = 0u; s_c[tid + 1024] = 0u;
    s_s[tid] = 0.f; s_s[tid + 1024] = 0.f;

    long long kk = 3LL * np; if (kk > AA) kk = AA;
    const unsigned k = (unsigned)kk;

    double rowtot = 0.0;

    if (k > 0) {
        // ---- bracket k in the 12-bit histogram (4 bins/thread) — overlapped ---
        const unsigned c4[4] = {cv.x, cv.y, cv.z, cv.w};
        {
            const unsigned tot = c4[0] + c4[1] + c4[2] + c4[3];
            const unsigned A = suffix_scan(tot, tid);
            unsigned ab = A - tot;               // strictly above my 4 bins
            #pragma unroll
            for (int j = 3; j >= 0; --j) {       // high bin -> low bin
                if (ab < k && k <= ab + c4[j]) {
                    s_d0 = (unsigned)(tid * 4 + j); s_kr = k - ab; s_cb = c4[j];
                }
                ab += c4[j];
            }
        }
        __syncthreads();                         // publish d0 + refine zeros
        const unsigned d0 = s_d0, krem = s_kr, cbin = s_cb;

        // reset my hist bins now (read already latched into c4)
        *(uint4*)(g_hist + b * HB + tid * 4) = make_uint4(0u, 0u, 0u, 0u);

        // ---- process the prefetched row data (already landed) ----
        double sumA = 0.0;
        #pragma unroll
        for (int it = 0; it < 8; ++it) {
            const float xs[4] = {r[it].x, r[it].y, r[it].z, r[it].w};
            #pragma unroll
            for (int e = 0; e < 4; ++e) {
                const float x = xs[e];
                const unsigned key = tokey(x);
                const unsigned dg  = key >> 20;
                if (dg > d0) sumA += (double)x;
                else if (dg == d0) {             // ~3-5%: spread bins
                    const unsigned rr = (key >> 9) & (RB - 1u);
                    atomicAdd(&s_c[rr], 1u);
                    atomicAdd(&s_s[rr], x);
                }
            }
        }
        __syncthreads();

        double inbin;
        if (krem == cbin) {              // whole boundary bin included: exact
            inbin = (double)s_s[tid] + (double)s_s[tid + 1024];
        } else {
            // ---- bracket krem in the refine hist (2 bins/thread) ----
            const unsigned c2[2] = {s_c[tid * 2], s_c[tid * 2 + 1]};
            const unsigned tot = c2[0] + c2[1];
            const unsigned A = suffix_scan(tot, tid);
            unsigned ab = A - tot;
            #pragma unroll
            for (int j = 1; j >= 0; --j) {
                if (ab < krem && krem <= ab + c2[j]) {
                    s_d1 = (unsigned)(tid * 2 + j); s_k2 = krem - ab;
                }
                ab += c2[j];
            }
            __syncthreads();
            const unsigned d1 = s_d1, k2 = s_k2;
            double la = 0.0;
            if ((unsigned)(tid * 2)     > d1) la += (double)s_s[tid * 2];
            if ((unsigned)(tid * 2 + 1) > d1) la += (double)s_s[tid * 2 + 1];
            inbin = la;
            if (tid == 0)                // ties at 23-bit prefix base (err<=2^-14)
                inbin += (double)k2 * (double)fromkey((d0 << 20) | (d1 << 9));
        }
        const double t = dsum(sumA + inbin, tid);  // ONE fused block reduction
        if (tid == 0) rowtot = t;
    } else {
        // still reset the hist (it may be nonzero even if np==0? k==0 => no
        // positives; hist was still built, so reset it)
        *(uint4*)(g_hist + b * HB + tid * 4) = make_uint4(0u, 0u, 0u, 0u);
    }

    if (tid == 0) {
        rowtot += g_locr[b] + g_pcer[b];
        atomicAdd(&g_fsum, rowtot);      // fire-and-forget REDs
        atomicAdd(&g_fnp, np);
        g_locr[b] = 0.0; g_pcer[b] = 0.0; g_numpos[b] = 0;
        const int tk = fetch_add_acqrel(&g_ticket);   // 32 total: negligible
        if (tk == BB - 1) {              // global last finisher
            const double fs = atomicAdd(&g_fsum, 0.0);
            const int    fn = atomicAdd(&g_fnp, 0);
            out[0] = (float)(fs / (double)fn);
            g_fsum = 0.0; g_fnp = 0; g_ticket = 0;
        }
    }
}

// ---------------- launch (2 kernels) ----------------
extern "C" void kernel_launch(void* const* d_in, const int* in_sizes, int n_in,
                              void* d_out, int out_size)
{
    const float* loc_p = (const float*)d_in[0];
    const float* loc_t = (const float*)d_in[1];
    const float* cls_p = (const float*)d_in[2];
    const int*   cls_t = (const int*)d_in[3];

    dim3 grid1(AA / TILE, BB);
    ce_kernel<<<grid1, TILE>>>(loc_p, loc_t, cls_p, cls_t);
    select_kernel<<<BB, 1024>>>((float*)d_out);
}